// round 2
// baseline (speedup 1.0000x reference)
#include <cuda_runtime.h>

#define NN 50000
#define FF 64
#define HH 128
#define GG 512
#define BN_EPSF 1e-3f

// ---------------- scratch (device globals; no dynamic alloc allowed) ----------
static __device__ float  g_y[NN * HH];     // pre-GEMM output (pre-BN)
static __device__ float  g_a[NN * HH];     // A = h @ (W1-W2) + b_cn
static __device__ float  g_b[NN * HH];     // B = h @ W2
static __device__ float  g_p[GG * HH];     // pooled per-graph sums
static __device__ float  g_y2[GG * HH];    // post-GEMM output (pre-BN)
static __device__ float  g_sum1[HH];
static __device__ float  g_sumsq1[HH];
static __device__ double g_sum2[HH];
static __device__ double g_sumsq2[HH];

// ---------------- zero accumulators ----------------
__global__ void kzero() {
    int t = blockIdx.x * blockDim.x + threadIdx.x;
    if (t < GG * HH) g_p[t] = 0.f;
    if (t < HH) {
        g_sum1[t] = 0.f; g_sumsq1[t] = 0.f;
        g_sum2[t] = 0.0; g_sumsq2[t] = 0.0;
    }
}

// ---------------- K1: y = x @ w_pre + b_pre ; per-column sum/sumsq -----------
// blockDim 128 (one thread per output column), w_pre column held in registers.
__global__ void __launch_bounds__(128) k1(const float* __restrict__ x,
                                          const float* __restrict__ wpre,
                                          const float* __restrict__ bpre) {
    __shared__ __align__(16) float xs[8 * FF];
    const int t = threadIdx.x;
    float w[FF];
#pragma unroll
    for (int k = 0; k < FF; k++) w[k] = wpre[k * HH + t];
    const float bc = bpre[t];
    const int ROWS = 176;
    const int r0 = blockIdx.x * ROWS;
    const int r1 = min(NN, r0 + ROWS);
    float ls = 0.f, lq = 0.f;
    for (int rt = r0; rt < r1; rt += 8) {
        const int nr = min(8, r1 - rt);
        __syncthreads();
        for (int idx = t; idx < nr * FF; idx += 128) xs[idx] = x[rt * FF + idx];
        __syncthreads();
        for (int i = 0; i < nr; i++) {
            float acc = bc;
            const float4* xv4 = (const float4*)&xs[i * FF];
#pragma unroll
            for (int k4 = 0; k4 < FF / 4; k4++) {
                float4 xv = xv4[k4];
                acc = fmaf(xv.x, w[4 * k4 + 0], acc);
                acc = fmaf(xv.y, w[4 * k4 + 1], acc);
                acc = fmaf(xv.z, w[4 * k4 + 2], acc);
                acc = fmaf(xv.w, w[4 * k4 + 3], acc);
            }
            g_y[(rt + i) * HH + t] = acc;
            ls += acc;
            lq = fmaf(acc, acc, lq);
        }
    }
    atomicAdd(&g_sum1[t], ls);
    atomicAdd(&g_sumsq1[t], lq);
}

// ---------------- K2: h = relu(BN(y)); A = h@(W1-W2)+b_cn; B = h@W2 ----------
// 256 threads, 16-row x 256-col tiles, 4x4 register blocking per thread.
__global__ void __launch_bounds__(256) k2(const float* __restrict__ wcn,
                                          const float* __restrict__ bcn,
                                          const float* __restrict__ gpre,
                                          const float* __restrict__ bepre) {
    extern __shared__ __align__(16) float sm[];
    float* Wc = sm;                 // [128][256]: cols 0..127 = W1-W2, 128..255 = W2
    float* hs = sm + HH * 2 * HH;   // [16][128]
    __shared__ float hscale[HH], hbias[HH], bcn_s[HH];
    const int t = threadIdx.x;
    for (int idx = t; idx < HH * 2 * HH; idx += 256) {
        int k = idx >> 8;
        int c = idx & 255;
        int cc = c & 127;
        float w2 = wcn[(k + HH) * HH + cc];
        Wc[idx] = (c < HH) ? (wcn[k * HH + cc] - w2) : w2;
    }
    if (t < HH) {
        float mu  = g_sum1[t] * (1.f / NN);
        float var = g_sumsq1[t] * (1.f / NN) - mu * mu;
        float sc  = gpre[t] * rsqrtf(var + BN_EPSF);
        hscale[t] = sc;
        hbias[t]  = bepre[t] - mu * sc;
        bcn_s[t]  = bcn[t];
    }
    __syncthreads();
    const int c0 = (t & 63) * 4;     // output column group (0..255 in steps of 4)
    const int rg = (t >> 6) * 4;     // row group within tile
    const int r0 = blockIdx.x * 352;
    const int r1 = min(NN, r0 + 352);
    for (int rt = r0; rt < r1; rt += 16) {
        const int nr = min(16, r1 - rt);
        __syncthreads();
        for (int idx = t; idx < 16 * HH; idx += 256) {
            int i = idx >> 7;
            int k = idx & 127;
            float v = 0.f;
            if (i < nr) {
                float yv = g_y[(rt + i) * HH + k];
                v = fmaxf(fmaf(yv, hscale[k], hbias[k]), 0.f);
            }
            hs[idx] = v;
        }
        __syncthreads();
        float acc[4][4];
#pragma unroll
        for (int i = 0; i < 4; i++)
#pragma unroll
            for (int j = 0; j < 4; j++)
                acc[i][j] = (c0 < HH) ? bcn_s[c0 + j] : 0.f;
#pragma unroll 2
        for (int k0 = 0; k0 < HH; k0 += 4) {
            float4 w0 = *(const float4*)&Wc[(k0 + 0) * 256 + c0];
            float4 w1 = *(const float4*)&Wc[(k0 + 1) * 256 + c0];
            float4 w2 = *(const float4*)&Wc[(k0 + 2) * 256 + c0];
            float4 w3 = *(const float4*)&Wc[(k0 + 3) * 256 + c0];
#pragma unroll
            for (int i = 0; i < 4; i++) {
                float4 hv = *(const float4*)&hs[(rg + i) * HH + k0];
                acc[i][0] = fmaf(hv.x, w0.x, acc[i][0]);
                acc[i][1] = fmaf(hv.x, w0.y, acc[i][1]);
                acc[i][2] = fmaf(hv.x, w0.z, acc[i][2]);
                acc[i][3] = fmaf(hv.x, w0.w, acc[i][3]);
                acc[i][0] = fmaf(hv.y, w1.x, acc[i][0]);
                acc[i][1] = fmaf(hv.y, w1.y, acc[i][1]);
                acc[i][2] = fmaf(hv.y, w1.z, acc[i][2]);
                acc[i][3] = fmaf(hv.y, w1.w, acc[i][3]);
                acc[i][0] = fmaf(hv.z, w2.x, acc[i][0]);
                acc[i][1] = fmaf(hv.z, w2.y, acc[i][1]);
                acc[i][2] = fmaf(hv.z, w2.z, acc[i][2]);
                acc[i][3] = fmaf(hv.z, w2.w, acc[i][3]);
                acc[i][0] = fmaf(hv.w, w3.x, acc[i][0]);
                acc[i][1] = fmaf(hv.w, w3.y, acc[i][1]);
                acc[i][2] = fmaf(hv.w, w3.z, acc[i][2]);
                acc[i][3] = fmaf(hv.w, w3.w, acc[i][3]);
            }
        }
#pragma unroll
        for (int i = 0; i < 4; i++) {
            int row = rt + rg + i;
            if (row < r1) {
                float4 v = make_float4(acc[i][0], acc[i][1], acc[i][2], acc[i][3]);
                if (c0 < HH) *(float4*)&g_a[row * HH + c0] = v;
                else         *(float4*)&g_b[row * HH + (c0 - HH)] = v;
            }
        }
    }
}

// ---------------- K3: edge kernel -> direct graph pooling --------------------
__device__ __forceinline__ void red_add_v4(float* p, float4 v) {
    asm volatile("red.global.add.v4.f32 [%0], {%1, %2, %3, %4};"
                 :: "l"(p), "f"(v.x), "f"(v.y), "f"(v.z), "f"(v.w) : "memory");
}

__global__ void __launch_bounds__(256) k3(const int* __restrict__ src,
                                          const int* __restrict__ dst,
                                          const int* __restrict__ seg, int E) {
    const int e = (blockIdx.x * 256 + threadIdx.x) >> 5;
    if (e >= E) return;
    const int lane = threadIdx.x & 31;
    const int s = __ldg(src + e);
    const int d = __ldg(dst + e);
    const int g = __ldg(seg + s);
    float4 av = *(const float4*)&g_a[s * HH + lane * 4];
    float4 bv = *(const float4*)&g_b[d * HH + lane * 4];
    float4 m;
    m.x = fmaxf(av.x + bv.x, 0.f);
    m.y = fmaxf(av.y + bv.y, 0.f);
    m.z = fmaxf(av.z + bv.z, 0.f);
    m.w = fmaxf(av.w + bv.w, 0.f);
    red_add_v4(&g_p[g * HH + lane * 4], m);
}

// ---------------- K4: y2 = p @ w_post + b_post ; double col sums -------------
__global__ void __launch_bounds__(128) k4(const float* __restrict__ wpost,
                                          const float* __restrict__ bpost) {
    extern __shared__ float ws[];
    __shared__ float ps[HH];
    const int t = threadIdx.x;
    for (int i = t; i < HH * HH; i += 128) ws[i] = wpost[i];
    const float bc = bpost[t];
    const int r0 = blockIdx.x * (GG / 32);
    double bsum = 0.0, bsq = 0.0;
    __syncthreads();
    for (int r = r0; r < r0 + GG / 32; r++) {
        __syncthreads();
        ps[t] = g_p[r * HH + t];
        __syncthreads();
        float acc = bc;
#pragma unroll 8
        for (int k = 0; k < HH; k++) acc = fmaf(ps[k], ws[k * HH + t], acc);
        g_y2[r * HH + t] = acc;
        bsum += (double)acc;
        bsq = fma((double)acc, (double)acc, bsq);
    }
    atomicAdd(&g_sum2[t], bsum);
    atomicAdd(&g_sumsq2[t], bsq);
}

// ---------------- K5: relu(BN(y2)) @ w_out + b_out -> sigmoid ----------------
__global__ void __launch_bounds__(256) k5(const float* __restrict__ gpost,
                                          const float* __restrict__ bepost,
                                          const float* __restrict__ wout,
                                          const float* __restrict__ bout,
                                          float* __restrict__ out) {
    const int r = (blockIdx.x * 256 + threadIdx.x) >> 5;
    const int lane = threadIdx.x & 31;
    if (r >= GG) return;
    float acc = 0.f;
#pragma unroll
    for (int j = 0; j < 4; j++) {
        int c = lane + 32 * j;
        double mu = g_sum2[c] * (1.0 / GG);
        float var = (float)(g_sumsq2[c] * (1.0 / GG) - mu * mu);
        float sc = gpost[c] * rsqrtf(var + BN_EPSF);
        float hb = bepost[c] - (float)mu * sc;
        float hn = fmaxf(fmaf(g_y2[r * HH + c], sc, hb), 0.f);
        acc += hn * wout[c];
    }
#pragma unroll
    for (int o = 16; o; o >>= 1) acc += __shfl_down_sync(0xffffffffu, acc, o);
    if (lane == 0) out[r] = 1.f / (1.f + expf(-(acc + bout[0])));
}

// ---------------- launch -----------------------------------------------------
extern "C" void kernel_launch(void* const* d_in, const int* in_sizes, int n_in,
                              void* d_out, int out_size) {
    const float* x      = (const float*)d_in[0];
    const int*   src    = (const int*)d_in[1];
    const int*   dst    = (const int*)d_in[2];
    const int*   seg    = (const int*)d_in[3];
    const float* w_pre  = (const float*)d_in[4];
    const float* b_pre  = (const float*)d_in[5];
    const float* gm_pre = (const float*)d_in[6];
    const float* be_pre = (const float*)d_in[7];
    const float* w_cn   = (const float*)d_in[8];
    const float* b_cn   = (const float*)d_in[9];
    const float* w_post = (const float*)d_in[10];
    const float* b_post = (const float*)d_in[11];
    const float* gm_post= (const float*)d_in[12];
    const float* be_post= (const float*)d_in[13];
    const float* w_out  = (const float*)d_in[14];
    const float* b_out  = (const float*)d_in[15];
    float* out = (float*)d_out;
    const int E = in_sizes[1];

    const int k2_smem = (HH * 2 * HH + 16 * HH) * 4;   // 139264 B
    const int k4_smem = HH * HH * 4;                   // 65536 B
    cudaFuncSetAttribute(k2, cudaFuncAttributeMaxDynamicSharedMemorySize, k2_smem);
    cudaFuncSetAttribute(k4, cudaFuncAttributeMaxDynamicSharedMemorySize, k4_smem);

    kzero<<<(GG * HH + 255) / 256, 256>>>();
    k1<<<(NN + 175) / 176, 128>>>(x, w_pre, b_pre);
    k2<<<148, 256, k2_smem>>>(w_cn, b_cn, gm_pre, be_pre);
    k3<<<(E * 32 + 255) / 256, 256>>>(src, dst, seg, E);
    k4<<<32, 128, k4_smem>>>(w_post, b_post);
    k5<<<(GG * 32) / 256, 256>>>(gm_post, be_post, w_out, b_out, out);
}

// round 3
// speedup vs baseline: 1.0629x; 1.0629x over previous
#include <cuda_runtime.h>

#define NN 50000
#define EE_MAX 1600000
#define FF 64
#define HH 128
#define GG 512
#define BN_EPSF 1e-3f

// ---------------- scratch (device globals; no dynamic alloc allowed) ----------
static __device__ float  g_y[NN * HH];     // pre-GEMM output (pre-BN)
static __device__ float  g_a[NN * HH];     // A = h @ (W1-W2) + b_cn
static __device__ float  g_b[NN * HH];     // B = h @ W2
static __device__ float  g_p[GG * HH];     // pooled per-graph sums
static __device__ float  g_y2[GG * HH];    // post-GEMM output (pre-BN)
static __device__ float  g_sum1[HH];
static __device__ float  g_sumsq1[HH];
static __device__ double g_sum2[HH];
static __device__ double g_sumsq2[HH];
// CSR-by-src scratch
static __device__ int    g_cnt[NN];        // degree per src node
static __device__ int    g_off[NN];        // exclusive-scan offsets
static __device__ int    g_cur[NN];        // scatter cursors
static __device__ int    g_adj[EE_MAX];    // dst per edge, grouped by src

// ---------------- zero accumulators + counters ----------------
__global__ void kzero() {
    int t = blockIdx.x * blockDim.x + threadIdx.x;
    if (t < GG * HH) g_p[t] = 0.f;
    if (t < NN) g_cnt[t] = 0;
    if (t < HH) {
        g_sum1[t] = 0.f; g_sumsq1[t] = 0.f;
        g_sum2[t] = 0.0; g_sumsq2[t] = 0.0;
    }
}

// ---------------- CSR build: histogram ----------------
__global__ void khist(const int* __restrict__ src, int E) {
    int e = blockIdx.x * blockDim.x + threadIdx.x;
    if (e < E) atomicAdd(&g_cnt[__ldg(src + e)], 1);
}

// ---------------- CSR build: single-block exclusive scan over g_cnt ----------
__global__ void __launch_bounds__(1024) kscan() {
    __shared__ int sh[1024];
    __shared__ int carry_s;
    const int t = threadIdx.x;
    if (t == 0) carry_s = 0;
    __syncthreads();
    for (int base = 0; base < NN; base += 1024) {
        int i = base + t;
        int v = (i < NN) ? g_cnt[i] : 0;
        sh[t] = v;
        __syncthreads();
#pragma unroll
        for (int o = 1; o < 1024; o <<= 1) {
            int add = (t >= o) ? sh[t - o] : 0;
            __syncthreads();
            sh[t] += add;
            __syncthreads();
        }
        int excl = sh[t] - v + carry_s;
        if (i < NN) { g_off[i] = excl; g_cur[i] = excl; }
        __syncthreads();
        if (t == 1023) carry_s += sh[1023];
        __syncthreads();
    }
}

// ---------------- CSR build: scatter dst grouped by src ----------------
__global__ void kscat(const int* __restrict__ src, const int* __restrict__ dst,
                      int E) {
    int e = blockIdx.x * blockDim.x + threadIdx.x;
    if (e < E) {
        int s = __ldg(src + e);
        int pos = atomicAdd(&g_cur[s], 1);
        g_adj[pos] = __ldg(dst + e);
    }
}

// ---------------- K1: y = x @ w_pre + b_pre ; per-column sum/sumsq -----------
__global__ void __launch_bounds__(128) k1(const float* __restrict__ x,
                                          const float* __restrict__ wpre,
                                          const float* __restrict__ bpre) {
    __shared__ __align__(16) float xs[8 * FF];
    const int t = threadIdx.x;
    float w[FF];
#pragma unroll
    for (int k = 0; k < FF; k++) w[k] = wpre[k * HH + t];
    const float bc = bpre[t];
    const int ROWS = 176;
    const int r0 = blockIdx.x * ROWS;
    const int r1 = min(NN, r0 + ROWS);
    float ls = 0.f, lq = 0.f;
    for (int rt = r0; rt < r1; rt += 8) {
        const int nr = min(8, r1 - rt);
        __syncthreads();
        for (int idx = t; idx < nr * FF; idx += 128) xs[idx] = x[rt * FF + idx];
        __syncthreads();
        for (int i = 0; i < nr; i++) {
            float acc = bc;
            const float4* xv4 = (const float4*)&xs[i * FF];
#pragma unroll
            for (int k4 = 0; k4 < FF / 4; k4++) {
                float4 xv = xv4[k4];
                acc = fmaf(xv.x, w[4 * k4 + 0], acc);
                acc = fmaf(xv.y, w[4 * k4 + 1], acc);
                acc = fmaf(xv.z, w[4 * k4 + 2], acc);
                acc = fmaf(xv.w, w[4 * k4 + 3], acc);
            }
            g_y[(rt + i) * HH + t] = acc;
            ls += acc;
            lq = fmaf(acc, acc, lq);
        }
    }
    atomicAdd(&g_sum1[t], ls);
    atomicAdd(&g_sumsq1[t], lq);
}

// ---------------- K2: h = relu(BN(y)); A = h@(W1-W2)+b_cn; B = h@W2 ----------
__global__ void __launch_bounds__(256) k2(const float* __restrict__ wcn,
                                          const float* __restrict__ bcn,
                                          const float* __restrict__ gpre,
                                          const float* __restrict__ bepre) {
    extern __shared__ __align__(16) float sm[];
    float* Wc = sm;                 // [128][256]: cols 0..127 = W1-W2, 128..255 = W2
    float* hs = sm + HH * 2 * HH;   // [16][128]
    __shared__ float hscale[HH], hbias[HH], bcn_s[HH];
    const int t = threadIdx.x;
    for (int idx = t; idx < HH * 2 * HH; idx += 256) {
        int k = idx >> 8;
        int c = idx & 255;
        int cc = c & 127;
        float w2 = wcn[(k + HH) * HH + cc];
        Wc[idx] = (c < HH) ? (wcn[k * HH + cc] - w2) : w2;
    }
    if (t < HH) {
        float mu  = g_sum1[t] * (1.f / NN);
        float var = g_sumsq1[t] * (1.f / NN) - mu * mu;
        float sc  = gpre[t] * rsqrtf(var + BN_EPSF);
        hscale[t] = sc;
        hbias[t]  = bepre[t] - mu * sc;
        bcn_s[t]  = bcn[t];
    }
    __syncthreads();
    const int c0 = (t & 63) * 4;
    const int rg = (t >> 6) * 4;
    const int r0 = blockIdx.x * 352;
    const int r1 = min(NN, r0 + 352);
    for (int rt = r0; rt < r1; rt += 16) {
        const int nr = min(16, r1 - rt);
        __syncthreads();
        for (int idx = t; idx < 16 * HH; idx += 256) {
            int i = idx >> 7;
            int k = idx & 127;
            float v = 0.f;
            if (i < nr) {
                float yv = g_y[(rt + i) * HH + k];
                v = fmaxf(fmaf(yv, hscale[k], hbias[k]), 0.f);
            }
            hs[idx] = v;
        }
        __syncthreads();
        float acc[4][4];
#pragma unroll
        for (int i = 0; i < 4; i++)
#pragma unroll
            for (int j = 0; j < 4; j++)
                acc[i][j] = (c0 < HH) ? bcn_s[c0 + j] : 0.f;
#pragma unroll 2
        for (int k0 = 0; k0 < HH; k0 += 4) {
            float4 w0 = *(const float4*)&Wc[(k0 + 0) * 256 + c0];
            float4 w1 = *(const float4*)&Wc[(k0 + 1) * 256 + c0];
            float4 w2 = *(const float4*)&Wc[(k0 + 2) * 256 + c0];
            float4 w3 = *(const float4*)&Wc[(k0 + 3) * 256 + c0];
#pragma unroll
            for (int i = 0; i < 4; i++) {
                float4 hv = *(const float4*)&hs[(rg + i) * HH + k0];
                acc[i][0] = fmaf(hv.x, w0.x, acc[i][0]);
                acc[i][1] = fmaf(hv.x, w0.y, acc[i][1]);
                acc[i][2] = fmaf(hv.x, w0.z, acc[i][2]);
                acc[i][3] = fmaf(hv.x, w0.w, acc[i][3]);
                acc[i][0] = fmaf(hv.y, w1.x, acc[i][0]);
                acc[i][1] = fmaf(hv.y, w1.y, acc[i][1]);
                acc[i][2] = fmaf(hv.y, w1.z, acc[i][2]);
                acc[i][3] = fmaf(hv.y, w1.w, acc[i][3]);
                acc[i][0] = fmaf(hv.z, w2.x, acc[i][0]);
                acc[i][1] = fmaf(hv.z, w2.y, acc[i][1]);
                acc[i][2] = fmaf(hv.z, w2.z, acc[i][2]);
                acc[i][3] = fmaf(hv.z, w2.w, acc[i][3]);
                acc[i][0] = fmaf(hv.w, w3.x, acc[i][0]);
                acc[i][1] = fmaf(hv.w, w3.y, acc[i][1]);
                acc[i][2] = fmaf(hv.w, w3.z, acc[i][2]);
                acc[i][3] = fmaf(hv.w, w3.w, acc[i][3]);
            }
        }
#pragma unroll
        for (int i = 0; i < 4; i++) {
            int row = rt + rg + i;
            if (row < r1) {
                float4 v = make_float4(acc[i][0], acc[i][1], acc[i][2], acc[i][3]);
                if (c0 < HH) *(float4*)&g_a[row * HH + c0] = v;
                else         *(float4*)&g_b[row * HH + (c0 - HH)] = v;
            }
        }
    }
}

// ---------------- K3: one warp per node, CSR edge aggregation -> pool --------
__device__ __forceinline__ void red_add_v4(float* p, float4 v) {
    asm volatile("red.global.add.v4.f32 [%0], {%1, %2, %3, %4};"
                 :: "l"(p), "f"(v.x), "f"(v.y), "f"(v.z), "f"(v.w) : "memory");
}

__global__ void __launch_bounds__(256) k3(const int* __restrict__ seg) {
    const int i = (blockIdx.x * 256 + threadIdx.x) >> 5;
    if (i >= NN) return;
    const int lane = threadIdx.x & 31;
    const int deg = g_cnt[i];
    if (deg == 0) return;
    const float4 a = *(const float4*)&g_a[i * HH + lane * 4];
    const int g = __ldg(seg + i);
    const int* al = g_adj + g_off[i];
    float4 acc = make_float4(0.f, 0.f, 0.f, 0.f);
    int j = 0;
    for (; j + 4 <= deg; j += 4) {
        int d0 = __ldg(al + j + 0);
        int d1 = __ldg(al + j + 1);
        int d2 = __ldg(al + j + 2);
        int d3 = __ldg(al + j + 3);
        float4 b0 = *(const float4*)&g_b[d0 * HH + lane * 4];
        float4 b1 = *(const float4*)&g_b[d1 * HH + lane * 4];
        float4 b2 = *(const float4*)&g_b[d2 * HH + lane * 4];
        float4 b3 = *(const float4*)&g_b[d3 * HH + lane * 4];
        acc.x += fmaxf(a.x + b0.x, 0.f) + fmaxf(a.x + b1.x, 0.f)
               + fmaxf(a.x + b2.x, 0.f) + fmaxf(a.x + b3.x, 0.f);
        acc.y += fmaxf(a.y + b0.y, 0.f) + fmaxf(a.y + b1.y, 0.f)
               + fmaxf(a.y + b2.y, 0.f) + fmaxf(a.y + b3.y, 0.f);
        acc.z += fmaxf(a.z + b0.z, 0.f) + fmaxf(a.z + b1.z, 0.f)
               + fmaxf(a.z + b2.z, 0.f) + fmaxf(a.z + b3.z, 0.f);
        acc.w += fmaxf(a.w + b0.w, 0.f) + fmaxf(a.w + b1.w, 0.f)
               + fmaxf(a.w + b2.w, 0.f) + fmaxf(a.w + b3.w, 0.f);
    }
    for (; j < deg; j++) {
        int d = __ldg(al + j);
        float4 b = *(const float4*)&g_b[d * HH + lane * 4];
        acc.x += fmaxf(a.x + b.x, 0.f);
        acc.y += fmaxf(a.y + b.y, 0.f);
        acc.z += fmaxf(a.z + b.z, 0.f);
        acc.w += fmaxf(a.w + b.w, 0.f);
    }
    red_add_v4(&g_p[g * HH + lane * 4], acc);
}

// ---------------- K4: y2 = p @ w_post + b_post ; double col sums -------------
__global__ void __launch_bounds__(128) k4(const float* __restrict__ wpost,
                                          const float* __restrict__ bpost) {
    extern __shared__ float ws[];
    __shared__ float ps[HH];
    const int t = threadIdx.x;
    for (int i = t; i < HH * HH; i += 128) ws[i] = wpost[i];
    const float bc = bpost[t];
    const int r0 = blockIdx.x * (GG / 32);
    double bsum = 0.0, bsq = 0.0;
    __syncthreads();
    for (int r = r0; r < r0 + GG / 32; r++) {
        __syncthreads();
        ps[t] = g_p[r * HH + t];
        __syncthreads();
        float acc = bc;
#pragma unroll 8
        for (int k = 0; k < HH; k++) acc = fmaf(ps[k], ws[k * HH + t], acc);
        g_y2[r * HH + t] = acc;
        bsum += (double)acc;
        bsq = fma((double)acc, (double)acc, bsq);
    }
    atomicAdd(&g_sum2[t], bsum);
    atomicAdd(&g_sumsq2[t], bsq);
}

// ---------------- K5: relu(BN(y2)) @ w_out + b_out -> sigmoid ----------------
__global__ void __launch_bounds__(256) k5(const float* __restrict__ gpost,
                                          const float* __restrict__ bepost,
                                          const float* __restrict__ wout,
                                          const float* __restrict__ bout,
                                          float* __restrict__ out) {
    const int r = (blockIdx.x * 256 + threadIdx.x) >> 5;
    const int lane = threadIdx.x & 31;
    if (r >= GG) return;
    float acc = 0.f;
#pragma unroll
    for (int j = 0; j < 4; j++) {
        int c = lane + 32 * j;
        double mu = g_sum2[c] * (1.0 / GG);
        float var = (float)(g_sumsq2[c] * (1.0 / GG) - mu * mu);
        float sc = gpost[c] * rsqrtf(var + BN_EPSF);
        float hb = bepost[c] - (float)mu * sc;
        float hn = fmaxf(fmaf(g_y2[r * HH + c], sc, hb), 0.f);
        acc += hn * wout[c];
    }
#pragma unroll
    for (int o = 16; o; o >>= 1) acc += __shfl_down_sync(0xffffffffu, acc, o);
    if (lane == 0) out[r] = 1.f / (1.f + expf(-(acc + bout[0])));
}

// ---------------- launch -----------------------------------------------------
extern "C" void kernel_launch(void* const* d_in, const int* in_sizes, int n_in,
                              void* d_out, int out_size) {
    const float* x      = (const float*)d_in[0];
    const int*   src    = (const int*)d_in[1];
    const int*   dst    = (const int*)d_in[2];
    const int*   seg    = (const int*)d_in[3];
    const float* w_pre  = (const float*)d_in[4];
    const float* b_pre  = (const float*)d_in[5];
    const float* gm_pre = (const float*)d_in[6];
    const float* be_pre = (const float*)d_in[7];
    const float* w_cn   = (const float*)d_in[8];
    const float* b_cn   = (const float*)d_in[9];
    const float* w_post = (const float*)d_in[10];
    const float* b_post = (const float*)d_in[11];
    const float* gm_post= (const float*)d_in[12];
    const float* be_post= (const float*)d_in[13];
    const float* w_out  = (const float*)d_in[14];
    const float* b_out  = (const float*)d_in[15];
    float* out = (float*)d_out;
    const int E = in_sizes[1];

    const int k2_smem = (HH * 2 * HH + 16 * HH) * 4;   // 139264 B
    const int k4_smem = HH * HH * 4;                   // 65536 B
    cudaFuncSetAttribute(k2, cudaFuncAttributeMaxDynamicSharedMemorySize, k2_smem);
    cudaFuncSetAttribute(k4, cudaFuncAttributeMaxDynamicSharedMemorySize, k4_smem);

    kzero<<<(GG * HH + 255) / 256, 256>>>();
    khist<<<(E + 511) / 512, 512>>>(src, E);
    kscan<<<1, 1024>>>();
    kscat<<<(E + 511) / 512, 512>>>(src, dst, E);
    k1<<<(NN + 175) / 176, 128>>>(x, w_pre, b_pre);
    k2<<<148, 256, k2_smem>>>(w_cn, b_cn, gm_pre, be_pre);
    k3<<<(NN * 32 + 255) / 256, 256>>>(seg);
    k4<<<32, 128, k4_smem>>>(w_post, b_post);
    k5<<<(GG * 32) / 256, 256>>>(gm_post, be_post, w_out, b_out, out);
}

// round 4
// speedup vs baseline: 1.3133x; 1.2355x over previous
#include <cuda_runtime.h>

#define NN 50000
#define EE_MAX 1600000
#define FF 64
#define HH 128
#define GG 512
#define BN_EPSF 1e-3f

// ---------------- scratch (device globals; no dynamic alloc allowed) ----------
static __device__ float  g_y[NN * HH];     // pre-GEMM output (pre-BN)
static __device__ float  g_a[NN * HH];     // A = h @ (W1-W2) + b_cn
static __device__ float  g_b[NN * HH];     // B = h @ W2
static __device__ float  g_p[GG * HH];     // pooled per-graph sums
static __device__ float  g_y2[GG * HH];    // post-GEMM output (pre-BN)
static __device__ float  g_sum1[HH];
static __device__ float  g_sumsq1[HH];
static __device__ double g_sum2[HH];
static __device__ double g_sumsq2[HH];
// CSR-by-src scratch
static __device__ int    g_cnt[NN];        // degree per src node
static __device__ int    g_off[NN];        // exclusive-scan offsets
static __device__ int    g_cur[NN];        // scatter cursors
static __device__ int    g_adj[EE_MAX];    // dst per edge, grouped by src

// ---------------- zero accumulators + counters ----------------
__global__ void kzero() {
    int t = blockIdx.x * blockDim.x + threadIdx.x;
    if (t < GG * HH) g_p[t] = 0.f;
    if (t < NN) g_cnt[t] = 0;
    if (t < HH) {
        g_sum1[t] = 0.f; g_sumsq1[t] = 0.f;
        g_sum2[t] = 0.0; g_sumsq2[t] = 0.0;
    }
}

// ---------------- CSR build: histogram (4 edges/thread for MLP) --------------
__global__ void khist(const int* __restrict__ src, int E) {
    int base = (blockIdx.x * blockDim.x + threadIdx.x) * 4;
#pragma unroll
    for (int u = 0; u < 4; u++) {
        int e = base + u;
        if (e < E) atomicAdd(&g_cnt[__ldg(src + e)], 1);
    }
}

// ---------------- CSR build: fast single-block exclusive scan ----------------
__global__ void __launch_bounds__(1024) kscan() {
    const int t = threadIdx.x;
    const int CH = (NN + 1023) / 1024;   // 49
    const int s0 = t * CH;
    const int s1 = min(NN, s0 + CH);
    int lsum = 0;
    for (int i = s0; i < s1; i++) lsum += g_cnt[i];
    const int lane = t & 31, wid = t >> 5;
    int v = lsum;
#pragma unroll
    for (int o = 1; o < 32; o <<= 1) {
        int n = __shfl_up_sync(0xffffffffu, v, o);
        if (lane >= o) v += n;
    }
    __shared__ int wsum[32];
    if (lane == 31) wsum[wid] = v;
    __syncthreads();
    if (wid == 0) {
        int w = wsum[lane];
#pragma unroll
        for (int o = 1; o < 32; o <<= 1) {
            int n = __shfl_up_sync(0xffffffffu, w, o);
            if (lane >= o) w += n;
        }
        wsum[lane] = w;
    }
    __syncthreads();
    int excl = v - lsum + (wid ? wsum[wid - 1] : 0);
    for (int i = s0; i < s1; i++) {
        int c = g_cnt[i];
        g_off[i] = excl;
        g_cur[i] = excl;
        excl += c;
    }
}

// ---------------- CSR build: scatter (4 edges/thread for MLP) ----------------
__global__ void kscat(const int* __restrict__ src, const int* __restrict__ dst,
                      int E) {
    int base = (blockIdx.x * blockDim.x + threadIdx.x) * 4;
#pragma unroll
    for (int u = 0; u < 4; u++) {
        int e = base + u;
        if (e < E) {
            int s = __ldg(src + e);
            int pos = atomicAdd(&g_cur[s], 1);
            g_adj[pos] = __ldg(dst + e);
        }
    }
}

// ---------------- K1: y = x @ w_pre + b_pre ; per-column sum/sumsq -----------
__global__ void __launch_bounds__(128) k1(const float* __restrict__ x,
                                          const float* __restrict__ wpre,
                                          const float* __restrict__ bpre) {
    __shared__ __align__(16) float xs[8 * FF];
    const int t = threadIdx.x;
    float w[FF];
#pragma unroll
    for (int k = 0; k < FF; k++) w[k] = wpre[k * HH + t];
    const float bc = bpre[t];
    const int ROWS = 176;
    const int r0 = blockIdx.x * ROWS;
    const int r1 = min(NN, r0 + ROWS);
    float ls = 0.f, lq = 0.f;
    for (int rt = r0; rt < r1; rt += 8) {
        const int nr = min(8, r1 - rt);
        __syncthreads();
        for (int idx = t; idx < nr * FF; idx += 128) xs[idx] = x[rt * FF + idx];
        __syncthreads();
        for (int i = 0; i < nr; i++) {
            float acc = bc;
            const float4* xv4 = (const float4*)&xs[i * FF];
#pragma unroll
            for (int k4 = 0; k4 < FF / 4; k4++) {
                float4 xv = xv4[k4];
                acc = fmaf(xv.x, w[4 * k4 + 0], acc);
                acc = fmaf(xv.y, w[4 * k4 + 1], acc);
                acc = fmaf(xv.z, w[4 * k4 + 2], acc);
                acc = fmaf(xv.w, w[4 * k4 + 3], acc);
            }
            g_y[(rt + i) * HH + t] = acc;
            ls += acc;
            lq = fmaf(acc, acc, lq);
        }
    }
    atomicAdd(&g_sum1[t], ls);
    atomicAdd(&g_sumsq1[t], lq);
}

// ---------------- K2: h = relu(BN(y)); A = h@(W1-W2)+b_cn; B = h@W2 ----------
__global__ void __launch_bounds__(256) k2(const float* __restrict__ wcn,
                                          const float* __restrict__ bcn,
                                          const float* __restrict__ gpre,
                                          const float* __restrict__ bepre) {
    extern __shared__ __align__(16) float sm[];
    float* Wc = sm;                 // [128][256]: cols 0..127 = W1-W2, 128..255 = W2
    float* hs = sm + HH * 2 * HH;   // [16][128]
    __shared__ float hscale[HH], hbias[HH], bcn_s[HH];
    const int t = threadIdx.x;
    for (int idx = t; idx < HH * 2 * HH; idx += 256) {
        int k = idx >> 8;
        int c = idx & 255;
        int cc = c & 127;
        float w2 = wcn[(k + HH) * HH + cc];
        Wc[idx] = (c < HH) ? (wcn[k * HH + cc] - w2) : w2;
    }
    if (t < HH) {
        float mu  = g_sum1[t] * (1.f / NN);
        float var = g_sumsq1[t] * (1.f / NN) - mu * mu;
        float sc  = gpre[t] * rsqrtf(var + BN_EPSF);
        hscale[t] = sc;
        hbias[t]  = bepre[t] - mu * sc;
        bcn_s[t]  = bcn[t];
    }
    __syncthreads();
    const int c0 = (t & 63) * 4;
    const int rg = (t >> 6) * 4;
    const int r0 = blockIdx.x * 352;
    const int r1 = min(NN, r0 + 352);
    for (int rt = r0; rt < r1; rt += 16) {
        const int nr = min(16, r1 - rt);
        __syncthreads();
        for (int idx = t; idx < 16 * HH; idx += 256) {
            int i = idx >> 7;
            int k = idx & 127;
            float v = 0.f;
            if (i < nr) {
                float yv = g_y[(rt + i) * HH + k];
                v = fmaxf(fmaf(yv, hscale[k], hbias[k]), 0.f);
            }
            hs[idx] = v;
        }
        __syncthreads();
        float acc[4][4];
#pragma unroll
        for (int i = 0; i < 4; i++)
#pragma unroll
            for (int j = 0; j < 4; j++)
                acc[i][j] = (c0 < HH) ? bcn_s[c0 + j] : 0.f;
#pragma unroll 2
        for (int k0 = 0; k0 < HH; k0 += 4) {
            float4 w0 = *(const float4*)&Wc[(k0 + 0) * 256 + c0];
            float4 w1 = *(const float4*)&Wc[(k0 + 1) * 256 + c0];
            float4 w2 = *(const float4*)&Wc[(k0 + 2) * 256 + c0];
            float4 w3 = *(const float4*)&Wc[(k0 + 3) * 256 + c0];
#pragma unroll
            for (int i = 0; i < 4; i++) {
                float4 hv = *(const float4*)&hs[(rg + i) * HH + k0];
                acc[i][0] = fmaf(hv.x, w0.x, acc[i][0]);
                acc[i][1] = fmaf(hv.x, w0.y, acc[i][1]);
                acc[i][2] = fmaf(hv.x, w0.z, acc[i][2]);
                acc[i][3] = fmaf(hv.x, w0.w, acc[i][3]);
                acc[i][0] = fmaf(hv.y, w1.x, acc[i][0]);
                acc[i][1] = fmaf(hv.y, w1.y, acc[i][1]);
                acc[i][2] = fmaf(hv.y, w1.z, acc[i][2]);
                acc[i][3] = fmaf(hv.y, w1.w, acc[i][3]);
                acc[i][0] = fmaf(hv.z, w2.x, acc[i][0]);
                acc[i][1] = fmaf(hv.z, w2.y, acc[i][1]);
                acc[i][2] = fmaf(hv.z, w2.z, acc[i][2]);
                acc[i][3] = fmaf(hv.z, w2.w, acc[i][3]);
                acc[i][0] = fmaf(hv.w, w3.x, acc[i][0]);
                acc[i][1] = fmaf(hv.w, w3.y, acc[i][1]);
                acc[i][2] = fmaf(hv.w, w3.z, acc[i][2]);
                acc[i][3] = fmaf(hv.w, w3.w, acc[i][3]);
            }
        }
#pragma unroll
        for (int i = 0; i < 4; i++) {
            int row = rt + rg + i;
            if (row < r1) {
                float4 v = make_float4(acc[i][0], acc[i][1], acc[i][2], acc[i][3]);
                if (c0 < HH) *(float4*)&g_a[row * HH + c0] = v;
                else         *(float4*)&g_b[row * HH + (c0 - HH)] = v;
            }
        }
    }
}

// ---------------- K3: one warp per node, CSR edge aggregation -> pool --------
__device__ __forceinline__ void red_add_v4(float* p, float4 v) {
    asm volatile("red.global.add.v4.f32 [%0], {%1, %2, %3, %4};"
                 :: "l"(p), "f"(v.x), "f"(v.y), "f"(v.z), "f"(v.w) : "memory");
}

__global__ void __launch_bounds__(256) k3(const int* __restrict__ seg) {
    const int i = (blockIdx.x * 256 + threadIdx.x) >> 5;
    if (i >= NN) return;
    const int lane = threadIdx.x & 31;
    const int deg = g_cnt[i];
    if (deg == 0) return;
    const float4 a = *(const float4*)&g_a[i * HH + lane * 4];
    const int g = __ldg(seg + i);
    const int* al = g_adj + g_off[i];
    float4 acc = make_float4(0.f, 0.f, 0.f, 0.f);
    int j = 0;
    for (; j + 8 <= deg; j += 8) {
        int d[8];
#pragma unroll
        for (int u = 0; u < 8; u++) d[u] = __ldg(al + j + u);
#pragma unroll
        for (int u = 0; u < 8; u++) {
            float4 b = *(const float4*)&g_b[d[u] * HH + lane * 4];
            acc.x += fmaxf(a.x + b.x, 0.f);
            acc.y += fmaxf(a.y + b.y, 0.f);
            acc.z += fmaxf(a.z + b.z, 0.f);
            acc.w += fmaxf(a.w + b.w, 0.f);
        }
    }
    for (; j < deg; j++) {
        int d = __ldg(al + j);
        float4 b = *(const float4*)&g_b[d * HH + lane * 4];
        acc.x += fmaxf(a.x + b.x, 0.f);
        acc.y += fmaxf(a.y + b.y, 0.f);
        acc.z += fmaxf(a.z + b.z, 0.f);
        acc.w += fmaxf(a.w + b.w, 0.f);
    }
    red_add_v4(&g_p[g * HH + lane * 4], acc);
}

// ---------------- K4: y2 = p @ w_post + b_post ; double col sums -------------
__global__ void __launch_bounds__(128) k4(const float* __restrict__ wpost,
                                          const float* __restrict__ bpost) {
    extern __shared__ float ws[];
    __shared__ float ps[HH];
    const int t = threadIdx.x;
    for (int i = t; i < HH * HH; i += 128) ws[i] = wpost[i];
    const float bc = bpost[t];
    const int r0 = blockIdx.x * (GG / 32);
    double bsum = 0.0, bsq = 0.0;
    __syncthreads();
    for (int r = r0; r < r0 + GG / 32; r++) {
        __syncthreads();
        ps[t] = g_p[r * HH + t];
        __syncthreads();
        float acc = bc;
#pragma unroll 8
        for (int k = 0; k < HH; k++) acc = fmaf(ps[k], ws[k * HH + t], acc);
        g_y2[r * HH + t] = acc;
        bsum += (double)acc;
        bsq = fma((double)acc, (double)acc, bsq);
    }
    atomicAdd(&g_sum2[t], bsum);
    atomicAdd(&g_sumsq2[t], bsq);
}

// ---------------- K5: relu(BN(y2)) @ w_out + b_out -> sigmoid ----------------
__global__ void __launch_bounds__(256) k5(const float* __restrict__ gpost,
                                          const float* __restrict__ bepost,
                                          const float* __restrict__ wout,
                                          const float* __restrict__ bout,
                                          float* __restrict__ out) {
    const int r = (blockIdx.x * 256 + threadIdx.x) >> 5;
    const int lane = threadIdx.x & 31;
    if (r >= GG) return;
    float acc = 0.f;
#pragma unroll
    for (int j = 0; j < 4; j++) {
        int c = lane + 32 * j;
        double mu = g_sum2[c] * (1.0 / GG);
        float var = (float)(g_sumsq2[c] * (1.0 / GG) - mu * mu);
        float sc = gpost[c] * rsqrtf(var + BN_EPSF);
        float hb = bepost[c] - (float)mu * sc;
        float hn = fmaxf(fmaf(g_y2[r * HH + c], sc, hb), 0.f);
        acc += hn * wout[c];
    }
#pragma unroll
    for (int o = 16; o; o >>= 1) acc += __shfl_down_sync(0xffffffffu, acc, o);
    if (lane == 0) out[r] = 1.f / (1.f + expf(-(acc + bout[0])));
}

// ---------------- launch -----------------------------------------------------
extern "C" void kernel_launch(void* const* d_in, const int* in_sizes, int n_in,
                              void* d_out, int out_size) {
    const float* x      = (const float*)d_in[0];
    const int*   src    = (const int*)d_in[1];
    const int*   dst    = (const int*)d_in[2];
    const int*   seg    = (const int*)d_in[3];
    const float* w_pre  = (const float*)d_in[4];
    const float* b_pre  = (const float*)d_in[5];
    const float* gm_pre = (const float*)d_in[6];
    const float* be_pre = (const float*)d_in[7];
    const float* w_cn   = (const float*)d_in[8];
    const float* b_cn   = (const float*)d_in[9];
    const float* w_post = (const float*)d_in[10];
    const float* b_post = (const float*)d_in[11];
    const float* gm_post= (const float*)d_in[12];
    const float* be_post= (const float*)d_in[13];
    const float* w_out  = (const float*)d_in[14];
    const float* b_out  = (const float*)d_in[15];
    float* out = (float*)d_out;
    const int E = in_sizes[1];

    static cudaStream_t s2 = nullptr;
    static cudaEvent_t ev_fork = nullptr, ev_join = nullptr;
    if (!s2) {
        cudaStreamCreateWithFlags(&s2, cudaStreamNonBlocking);
        cudaEventCreateWithFlags(&ev_fork, cudaEventDisableTiming);
        cudaEventCreateWithFlags(&ev_join, cudaEventDisableTiming);
    }

    const int k2_smem = (HH * 2 * HH + 16 * HH) * 4;   // 139264 B
    const int k4_smem = HH * HH * 4;                   // 65536 B
    cudaFuncSetAttribute(k2, cudaFuncAttributeMaxDynamicSharedMemorySize, k2_smem);
    cudaFuncSetAttribute(k4, cudaFuncAttributeMaxDynamicSharedMemorySize, k4_smem);

    // main stream: zero everything (g_cnt needed by CSR branch)
    kzero<<<(GG * HH + 255) / 256, 256>>>();
    // fork: CSR build on s2, concurrent with k1+k2 on main stream
    cudaEventRecord(ev_fork, 0);
    cudaStreamWaitEvent(s2, ev_fork, 0);
    khist<<<(E / 4 + 511) / 512, 512, 0, s2>>>(src, E);
    kscan<<<1, 1024, 0, s2>>>();
    kscat<<<(E / 4 + 511) / 512, 512, 0, s2>>>(src, dst, E);
    cudaEventRecord(ev_join, s2);
    // main stream: node GEMMs
    k1<<<(NN + 175) / 176, 128>>>(x, w_pre, b_pre);
    k2<<<148, 256, k2_smem>>>(w_cn, b_cn, gm_pre, be_pre);
    // join: k3 needs CSR + A/B
    cudaStreamWaitEvent(0, ev_join, 0);
    k3<<<(NN * 32 + 255) / 256, 256>>>(seg);
    k4<<<32, 128, k4_smem>>>(w_post, b_post);
    k5<<<(GG * 32) / 256, 256>>>(gm_post, be_post, w_out, b_out, out);
}

// round 5
// speedup vs baseline: 1.5329x; 1.1672x over previous
#include <cuda_runtime.h>
#include <cstdint>

#define NN 50000
#define EE_MAX 1600000
#define FF 64
#define HH 128
#define GG 512
#define BN_EPSF 1e-3f

#define FMA2(d, a, b, c) \
    asm("fma.rn.f32x2 %0, %1, %2, %3;" : "=l"(d) : "l"(a), "l"(b), "l"(c))
#define PACK2(d, x) \
    asm("mov.b64 %0, {%1, %1};" : "=l"(d) : "f"(x))

// ---------------- scratch (device globals; no dynamic alloc allowed) ----------
static __device__ float    g_y[NN * HH];   // pre-GEMM output (pre-BN)
static __device__ float    g_a[NN * HH];   // A = h @ (W1-W2) + b_cn  (fp32)
static __device__ unsigned g_bh[NN * 64];  // B = h @ W2 as bf16x2 pairs
static __device__ float    g_p[GG * HH];   // pooled per-graph sums
static __device__ float    g_y2[GG * HH];  // post-GEMM output (pre-BN)
static __device__ float    g_sum1[HH];
static __device__ float    g_sumsq1[HH];
static __device__ double   g_sum2[HH];
static __device__ double   g_sumsq2[HH];
// CSR-by-src scratch
static __device__ int      g_cnt[NN];
static __device__ int      g_off[NN];
static __device__ int      g_cur[NN];
static __device__ int      g_adj[EE_MAX];

// ---------------- zero accumulators + counters ----------------
__global__ void kzero() {
    int t = blockIdx.x * blockDim.x + threadIdx.x;
    if (t < GG * HH) g_p[t] = 0.f;
    if (t < NN) g_cnt[t] = 0;
    if (t < HH) {
        g_sum1[t] = 0.f; g_sumsq1[t] = 0.f;
        g_sum2[t] = 0.0; g_sumsq2[t] = 0.0;
    }
}

// ---------------- CSR build: histogram (4 edges/thread for MLP) --------------
__global__ void khist(const int* __restrict__ src, int E) {
    int base = (blockIdx.x * blockDim.x + threadIdx.x) * 4;
#pragma unroll
    for (int u = 0; u < 4; u++) {
        int e = base + u;
        if (e < E) atomicAdd(&g_cnt[__ldg(src + e)], 1);
    }
}

// ---------------- CSR build: fast single-block exclusive scan ----------------
__global__ void __launch_bounds__(1024) kscan() {
    const int t = threadIdx.x;
    const int CH = (NN + 1023) / 1024;
    const int s0 = t * CH;
    const int s1 = min(NN, s0 + CH);
    int lsum = 0;
    for (int i = s0; i < s1; i++) lsum += g_cnt[i];
    const int lane = t & 31, wid = t >> 5;
    int v = lsum;
#pragma unroll
    for (int o = 1; o < 32; o <<= 1) {
        int n = __shfl_up_sync(0xffffffffu, v, o);
        if (lane >= o) v += n;
    }
    __shared__ int wsum[32];
    if (lane == 31) wsum[wid] = v;
    __syncthreads();
    if (wid == 0) {
        int w = wsum[lane];
#pragma unroll
        for (int o = 1; o < 32; o <<= 1) {
            int n = __shfl_up_sync(0xffffffffu, w, o);
            if (lane >= o) w += n;
        }
        wsum[lane] = w;
    }
    __syncthreads();
    int excl = v - lsum + (wid ? wsum[wid - 1] : 0);
    for (int i = s0; i < s1; i++) {
        int c = g_cnt[i];
        g_off[i] = excl;
        g_cur[i] = excl;
        excl += c;
    }
}

// ---------------- CSR build: scatter (4 edges/thread for MLP) ----------------
__global__ void kscat(const int* __restrict__ src, const int* __restrict__ dst,
                      int E) {
    int base = (blockIdx.x * blockDim.x + threadIdx.x) * 4;
#pragma unroll
    for (int u = 0; u < 4; u++) {
        int e = base + u;
        if (e < E) {
            int s = __ldg(src + e);
            int pos = atomicAdd(&g_cur[s], 1);
            g_adj[pos] = __ldg(dst + e);
        }
    }
}

// ---------------- K1: y = x @ w_pre + b_pre ; per-column sum/sumsq -----------
__global__ void __launch_bounds__(128) k1(const float* __restrict__ x,
                                          const float* __restrict__ wpre,
                                          const float* __restrict__ bpre) {
    __shared__ __align__(16) float xs[8 * FF];
    const int t = threadIdx.x;
    float w[FF];
#pragma unroll
    for (int k = 0; k < FF; k++) w[k] = wpre[k * HH + t];
    const float bc = bpre[t];
    const int ROWS = 176;
    const int r0 = blockIdx.x * ROWS;
    const int r1 = min(NN, r0 + ROWS);
    float ls = 0.f, lq = 0.f;
    for (int rt = r0; rt < r1; rt += 8) {
        const int nr = min(8, r1 - rt);
        __syncthreads();
        for (int idx = t; idx < nr * FF; idx += 128) xs[idx] = x[rt * FF + idx];
        __syncthreads();
        for (int i = 0; i < nr; i++) {
            float acc = bc;
            const float4* xv4 = (const float4*)&xs[i * FF];
#pragma unroll
            for (int k4 = 0; k4 < FF / 4; k4++) {
                float4 xv = xv4[k4];
                acc = fmaf(xv.x, w[4 * k4 + 0], acc);
                acc = fmaf(xv.y, w[4 * k4 + 1], acc);
                acc = fmaf(xv.z, w[4 * k4 + 2], acc);
                acc = fmaf(xv.w, w[4 * k4 + 3], acc);
            }
            g_y[(rt + i) * HH + t] = acc;
            ls += acc;
            lq = fmaf(acc, acc, lq);
        }
    }
    atomicAdd(&g_sum1[t], ls);
    atomicAdd(&g_sumsq1[t], lq);
}

// ---------------- K2: h = relu(BN(y)); A = h@(W1-W2)+b_cn (fp32);
//                  B = h@W2 (bf16). FFMA2 packed, 8x8 register tile. ----------
__global__ void __launch_bounds__(256) k2(const float* __restrict__ wcn,
                                          const float* __restrict__ bcn,
                                          const float* __restrict__ gpre,
                                          const float* __restrict__ bepre) {
    extern __shared__ __align__(16) float sm[];
    float* Wc = sm;                 // [128][256]: cols 0..127 = W1-W2, 128..255 = W2
    float* hs = sm + HH * 2 * HH;   // [64][128]
    __shared__ __align__(8) float hscale[HH], hbias[HH], bcn_s[HH];
    const int t = threadIdx.x;
    for (int idx = t; idx < HH * 2 * HH; idx += 256) {
        int k = idx >> 8;
        int c = idx & 255;
        int cc = c & 127;
        float w2 = wcn[(k + HH) * HH + cc];
        Wc[idx] = (c < HH) ? (wcn[k * HH + cc] - w2) : w2;
    }
    if (t < HH) {
        float mu  = g_sum1[t] * (1.f / NN);
        float var = g_sumsq1[t] * (1.f / NN) - mu * mu;
        float sc  = gpre[t] * rsqrtf(var + BN_EPSF);
        hscale[t] = sc;
        hbias[t]  = bepre[t] - mu * sc;
        bcn_s[t]  = bcn[t];
    }
    __syncthreads();
    const int c0 = (t & 31) * 8;     // 8 output columns (0..255)
    const int rg = (t >> 5) * 8;     // 8 rows within 64-row tile
    const int r0 = blockIdx.x * 352;
    const int r1 = min(NN, r0 + 352);
    for (int rt = r0; rt < r1; rt += 64) {
        const int nr = min(64, r1 - rt);
        __syncthreads();
        for (int idx = t; idx < 64 * HH; idx += 256) {
            int i = idx >> 7;
            int k = idx & 127;
            float v = 0.f;
            if (i < nr) {
                float yv = g_y[(rt + i) * HH + k];
                v = fmaxf(fmaf(yv, hscale[k], hbias[k]), 0.f);
            }
            hs[idx] = v;
        }
        __syncthreads();
        unsigned long long acc[8][4];
        if (c0 < HH) {
#pragma unroll
            for (int j = 0; j < 4; j++) {
                unsigned long long bb = *(const unsigned long long*)&bcn_s[c0 + 2 * j];
#pragma unroll
                for (int i = 0; i < 8; i++) acc[i][j] = bb;
            }
        } else {
#pragma unroll
            for (int i = 0; i < 8; i++)
#pragma unroll
                for (int j = 0; j < 4; j++) acc[i][j] = 0ull;
        }
#pragma unroll 1
        for (int k0 = 0; k0 < HH; k0 += 4) {
            float4 hv[8];
#pragma unroll
            for (int i = 0; i < 8; i++)
                hv[i] = *(const float4*)&hs[(rg + i) * HH + k0];
#pragma unroll
            for (int kk = 0; kk < 4; kk++) {
                ulonglong2 wA = *(const ulonglong2*)&Wc[(k0 + kk) * 256 + c0];
                ulonglong2 wB = *(const ulonglong2*)&Wc[(k0 + kk) * 256 + c0 + 4];
#pragma unroll
                for (int i = 0; i < 8; i++) {
                    float hk = (kk == 0) ? hv[i].x : (kk == 1) ? hv[i].y
                             : (kk == 2) ? hv[i].z : hv[i].w;
                    unsigned long long hp;
                    PACK2(hp, hk);
                    FMA2(acc[i][0], hp, wA.x, acc[i][0]);
                    FMA2(acc[i][1], hp, wA.y, acc[i][1]);
                    FMA2(acc[i][2], hp, wB.x, acc[i][2]);
                    FMA2(acc[i][3], hp, wB.y, acc[i][3]);
                }
            }
        }
#pragma unroll
        for (int i = 0; i < 8; i++) {
            int row = rt + rg + i;
            if (row < r1) {
                if (c0 < HH) {
#pragma unroll
                    for (int j = 0; j < 4; j++)
                        *(unsigned long long*)&g_a[row * HH + c0 + 2 * j] = acc[i][j];
                } else {
                    uint4 pk;
                    unsigned* pks = (unsigned*)&pk;
#pragma unroll
                    for (int j = 0; j < 4; j++) {
                        float lo, hi;
                        asm("mov.b64 {%0, %1}, %2;" : "=f"(lo), "=f"(hi) : "l"(acc[i][j]));
                        asm("cvt.rn.bf16x2.f32 %0, %1, %2;" : "=r"(pks[j]) : "f"(hi), "f"(lo));
                    }
                    *(uint4*)&g_bh[row * 64 + (c0 - HH) / 2] = pk;
                }
            }
        }
    }
}

// ---------------- K3: one warp per node, CSR aggregation (bf16 B) -> pool ----
__device__ __forceinline__ void red_add_v4(float* p, float4 v) {
    asm volatile("red.global.add.v4.f32 [%0], {%1, %2, %3, %4};"
                 :: "l"(p), "f"(v.x), "f"(v.y), "f"(v.z), "f"(v.w) : "memory");
}

__device__ __forceinline__ void acc_edge(float4& acc, const float4& a, uint2 rb) {
    float b0 = __int_as_float(rb.x << 16);
    float b1 = __int_as_float(rb.x & 0xffff0000u);
    float b2 = __int_as_float(rb.y << 16);
    float b3 = __int_as_float(rb.y & 0xffff0000u);
    acc.x += fmaxf(a.x + b0, 0.f);
    acc.y += fmaxf(a.y + b1, 0.f);
    acc.z += fmaxf(a.z + b2, 0.f);
    acc.w += fmaxf(a.w + b3, 0.f);
}

__global__ void __launch_bounds__(256) k3(const int* __restrict__ seg) {
    const int i = (blockIdx.x * 256 + threadIdx.x) >> 5;
    if (i >= NN) return;
    const int lane = threadIdx.x & 31;
    const int deg = g_cnt[i];
    if (deg == 0) return;
    const float4 a = *(const float4*)&g_a[i * HH + lane * 4];
    const int g = __ldg(seg + i);
    const int* al = g_adj + g_off[i];
    float4 acc = make_float4(0.f, 0.f, 0.f, 0.f);
    int j = 0;
    for (; j + 8 <= deg; j += 8) {
        int d[8];
#pragma unroll
        for (int u = 0; u < 8; u++) d[u] = __ldg(al + j + u);
        uint2 rb[8];
#pragma unroll
        for (int u = 0; u < 8; u++)
            rb[u] = *(const uint2*)&g_bh[d[u] * 64 + lane * 2];
#pragma unroll
        for (int u = 0; u < 8; u++) acc_edge(acc, a, rb[u]);
    }
    for (; j < deg; j++) {
        int d = __ldg(al + j);
        uint2 rb = *(const uint2*)&g_bh[d * 64 + lane * 2];
        acc_edge(acc, a, rb);
    }
    red_add_v4(&g_p[g * HH + lane * 4], acc);
}

// ---------------- K4: y2 = p @ w_post + b_post ; double col sums -------------
__global__ void __launch_bounds__(128) k4(const float* __restrict__ wpost,
                                          const float* __restrict__ bpost) {
    extern __shared__ float ws[];
    __shared__ float ps[HH];
    const int t = threadIdx.x;
    for (int i = t; i < HH * HH; i += 128) ws[i] = wpost[i];
    const float bc = bpost[t];
    const int r0 = blockIdx.x * (GG / 32);
    double bsum = 0.0, bsq = 0.0;
    __syncthreads();
    for (int r = r0; r < r0 + GG / 32; r++) {
        __syncthreads();
        ps[t] = g_p[r * HH + t];
        __syncthreads();
        float acc = bc;
#pragma unroll 8
        for (int k = 0; k < HH; k++) acc = fmaf(ps[k], ws[k * HH + t], acc);
        g_y2[r * HH + t] = acc;
        bsum += (double)acc;
        bsq = fma((double)acc, (double)acc, bsq);
    }
    atomicAdd(&g_sum2[t], bsum);
    atomicAdd(&g_sumsq2[t], bsq);
}

// ---------------- K5: relu(BN(y2)) @ w_out + b_out -> sigmoid ----------------
__global__ void __launch_bounds__(256) k5(const float* __restrict__ gpost,
                                          const float* __restrict__ bepost,
                                          const float* __restrict__ wout,
                                          const float* __restrict__ bout,
                                          float* __restrict__ out) {
    const int r = (blockIdx.x * 256 + threadIdx.x) >> 5;
    const int lane = threadIdx.x & 31;
    if (r >= GG) return;
    float acc = 0.f;
#pragma unroll
    for (int j = 0; j < 4; j++) {
        int c = lane + 32 * j;
        double mu = g_sum2[c] * (1.0 / GG);
        float var = (float)(g_sumsq2[c] * (1.0 / GG) - mu * mu);
        float sc = gpost[c] * rsqrtf(var + BN_EPSF);
        float hb = bepost[c] - (float)mu * sc;
        float hn = fmaxf(fmaf(g_y2[r * HH + c], sc, hb), 0.f);
        acc += hn * wout[c];
    }
#pragma unroll
    for (int o = 16; o; o >>= 1) acc += __shfl_down_sync(0xffffffffu, acc, o);
    if (lane == 0) out[r] = 1.f / (1.f + expf(-(acc + bout[0])));
}

// ---------------- launch -----------------------------------------------------
extern "C" void kernel_launch(void* const* d_in, const int* in_sizes, int n_in,
                              void* d_out, int out_size) {
    const float* x      = (const float*)d_in[0];
    const int*   src    = (const int*)d_in[1];
    const int*   dst    = (const int*)d_in[2];
    const int*   seg    = (const int*)d_in[3];
    const float* w_pre  = (const float*)d_in[4];
    const float* b_pre  = (const float*)d_in[5];
    const float* gm_pre = (const float*)d_in[6];
    const float* be_pre = (const float*)d_in[7];
    const float* w_cn   = (const float*)d_in[8];
    const float* b_cn   = (const float*)d_in[9];
    const float* w_post = (const float*)d_in[10];
    const float* b_post = (const float*)d_in[11];
    const float* gm_post= (const float*)d_in[12];
    const float* be_post= (const float*)d_in[13];
    const float* w_out  = (const float*)d_in[14];
    const float* b_out  = (const float*)d_in[15];
    float* out = (float*)d_out;
    const int E = in_sizes[1];

    static cudaStream_t s2 = nullptr;
    static cudaEvent_t ev_fork = nullptr, ev_join = nullptr;
    if (!s2) {
        cudaStreamCreateWithFlags(&s2, cudaStreamNonBlocking);
        cudaEventCreateWithFlags(&ev_fork, cudaEventDisableTiming);
        cudaEventCreateWithFlags(&ev_join, cudaEventDisableTiming);
    }

    const int k2_smem = (HH * 2 * HH + 64 * HH) * 4;   // 163840 B
    const int k4_smem = HH * HH * 4;                   // 65536 B
    cudaFuncSetAttribute(k2, cudaFuncAttributeMaxDynamicSharedMemorySize, k2_smem);
    cudaFuncSetAttribute(k4, cudaFuncAttributeMaxDynamicSharedMemorySize, k4_smem);

    // main stream: zero everything (g_cnt needed by CSR branch)
    kzero<<<(GG * HH + 255) / 256, 256>>>();
    // fork: CSR build on s2, concurrent with k1+k2 on main stream
    cudaEventRecord(ev_fork, 0);
    cudaStreamWaitEvent(s2, ev_fork, 0);
    khist<<<(E / 4 + 511) / 512, 512, 0, s2>>>(src, E);
    kscan<<<1, 1024, 0, s2>>>();
    kscat<<<(E / 4 + 511) / 512, 512, 0, s2>>>(src, dst, E);
    cudaEventRecord(ev_join, s2);
    // main stream: node GEMMs
    k1<<<(NN + 175) / 176, 128>>>(x, w_pre, b_pre);
    k2<<<148, 256, k2_smem>>>(w_cn, b_cn, gm_pre, be_pre);
    // join: k3 needs CSR + A/B
    cudaStreamWaitEvent(0, ev_join, 0);
    k3<<<(NN * 32 + 255) / 256, 256>>>(seg);
    k4<<<32, 128, k4_smem>>>(w_post, b_post);
    k5<<<(GG * 32) / 256, 256>>>(gm_post, be_post, w_out, b_out, out);
}